// round 1
// baseline (speedup 1.0000x reference)
#include <cuda_runtime.h>
#include <cuda_bf16.h>

// PoleInteraction:
//   dEnergy[e,c] = w[c]^2 * p[r][c] * p[s][c] * sum_ij vec[r,i,c] * M[e,i,j] * vec[s,j,c]
//   dx = segment_sum(dEnergy, receivers)
// where p = MLP(LayerNorm(x)).

#define NODES_MAX 50000
#define CCH 64

__device__ float g_p[NODES_MAX * CCH];  // MLP output scratch

// ---------------------------------------------------------------------------
// K1: LayerNorm + MLP (64 -> 128 silu -> 64), warp per 4 nodes, weights in smem
// ---------------------------------------------------------------------------
__global__ __launch_bounds__(256) void k_node(
    const float* __restrict__ x,
    const float* __restrict__ ln_s, const float* __restrict__ ln_b,
    const float* __restrict__ w1, const float* __restrict__ b1,
    const float* __restrict__ w2, const float* __restrict__ b2,
    int N)
{
    extern __shared__ float sm[];
    float* w1s = sm;                     // 64*128
    float* w2s = w1s + 64 * 128;         // 128*64
    float* xns = w2s + 128 * 64;         // 8 warps * 4 nodes * 64
    float* hs  = xns + 8 * 4 * 64;       // 8 warps * 4 nodes * 128

    int tid = threadIdx.x;
    // cooperative weight load (float4)
    for (int i = tid; i < (64 * 128) / 4; i += blockDim.x)
        reinterpret_cast<float4*>(w1s)[i] = reinterpret_cast<const float4*>(w1)[i];
    for (int i = tid; i < (128 * 64) / 4; i += blockDim.x)
        reinterpret_cast<float4*>(w2s)[i] = reinterpret_cast<const float4*>(w2)[i];
    __syncthreads();

    int warp = tid >> 5, lane = tid & 31;
    int node0 = (blockIdx.x * 8 + warp) * 4;
    if (node0 >= N) return;
    float* xn = xns + warp * 4 * 64;
    float* hh = hs  + warp * 4 * 128;

    float2 lns = reinterpret_cast<const float2*>(ln_s)[lane];
    float2 lnb = reinterpret_cast<const float2*>(ln_b)[lane];

    // LayerNorm for 4 nodes; thread owns channels 2*lane, 2*lane+1
    #pragma unroll
    for (int u = 0; u < 4; u++) {
        int n = node0 + u;
        float2 v = make_float2(0.f, 0.f);
        if (n < N) v = reinterpret_cast<const float2*>(x + (size_t)n * 64)[lane];
        float s  = v.x + v.y;
        float sq = v.x * v.x + v.y * v.y;
        #pragma unroll
        for (int o = 16; o; o >>= 1) {
            s  += __shfl_xor_sync(0xffffffffu, s,  o);
            sq += __shfl_xor_sync(0xffffffffu, sq, o);
        }
        float mean = s * (1.f / 64.f);
        float var  = sq * (1.f / 64.f) - mean * mean;
        float rstd = rsqrtf(var + 1e-5f);
        float2 o;
        o.x = (v.x - mean) * rstd * lns.x + lnb.x;
        o.y = (v.y - mean) * rstd * lns.y + lnb.y;
        reinterpret_cast<float2*>(xn + u * 64)[lane] = o;
    }
    __syncwarp();

    // Layer 1: thread computes h[4*lane .. 4*lane+3] for 4 nodes
    float4 bb1 = reinterpret_cast<const float4*>(b1)[lane];
    float4 acc0 = bb1, acc1 = bb1, acc2 = bb1, acc3 = bb1;
    #pragma unroll 4
    for (int c = 0; c < 64; c++) {
        float4 w = reinterpret_cast<float4*>(w1s + c * 128)[lane];
        float x0 = xn[0 * 64 + c], x1 = xn[1 * 64 + c];
        float x2 = xn[2 * 64 + c], x3 = xn[3 * 64 + c];
        acc0.x += x0 * w.x; acc0.y += x0 * w.y; acc0.z += x0 * w.z; acc0.w += x0 * w.w;
        acc1.x += x1 * w.x; acc1.y += x1 * w.y; acc1.z += x1 * w.z; acc1.w += x1 * w.w;
        acc2.x += x2 * w.x; acc2.y += x2 * w.y; acc2.z += x2 * w.z; acc2.w += x2 * w.w;
        acc3.x += x3 * w.x; acc3.y += x3 * w.y; acc3.z += x3 * w.z; acc3.w += x3 * w.w;
    }

    // silu + stage h
    {
        float4 a[4] = {acc0, acc1, acc2, acc3};
        #pragma unroll
        for (int u = 0; u < 4; u++) {
            float4 v = a[u];
            v.x = v.x / (1.f + __expf(-v.x));
            v.y = v.y / (1.f + __expf(-v.y));
            v.z = v.z / (1.f + __expf(-v.z));
            v.w = v.w / (1.f + __expf(-v.w));
            reinterpret_cast<float4*>(hh + u * 128)[lane] = v;
        }
    }
    __syncwarp();

    // Layer 2: thread computes p[2*lane], p[2*lane+1] for 4 nodes
    float2 bb2 = reinterpret_cast<const float2*>(b2)[lane];
    float2 p0 = bb2, p1 = bb2, p2 = bb2, p3 = bb2;
    #pragma unroll 4
    for (int k = 0; k < 128; k++) {
        float2 w = reinterpret_cast<float2*>(w2s + k * 64)[lane];
        float h0 = hh[0 * 128 + k], h1 = hh[1 * 128 + k];
        float h2 = hh[2 * 128 + k], h3 = hh[3 * 128 + k];
        p0.x += h0 * w.x; p0.y += h0 * w.y;
        p1.x += h1 * w.x; p1.y += h1 * w.y;
        p2.x += h2 * w.x; p2.y += h2 * w.y;
        p3.x += h3 * w.x; p3.y += h3 * w.y;
    }
    {
        float2 p[4] = {p0, p1, p2, p3};
        #pragma unroll
        for (int u = 0; u < 4; u++) {
            int n = node0 + u;
            if (n < N)
                reinterpret_cast<float2*>(g_p + (size_t)n * 64)[lane] = p[u];
        }
    }
}

// ---------------------------------------------------------------------------
// K2: edge phase. 16 threads per edge, each thread owns 4 channels (float4).
//   f_i = sum_j M[i][j]*vj_j ;  S = sum_i vi_i*f_i ;  d = w^2*pi*pj*S
//   vectorized red.global.add.v4.f32 scatter.
// ---------------------------------------------------------------------------
__global__ __launch_bounds__(256) void k_edge(
    const float* __restrict__ vec,
    const int*   __restrict__ senders,
    const int*   __restrict__ receivers,
    const float* __restrict__ Mm,
    const float* __restrict__ vw,
    float* __restrict__ out,
    int E)
{
    int t = blockIdx.x * blockDim.x + threadIdx.x;
    int e = t >> 4;
    if (e >= E) return;
    int l = t & 15;

    int s = __ldg(senders + e);
    int r = __ldg(receivers + e);

    const float* M = Mm + (size_t)e * 9;
    float m00 = __ldg(M + 0), m01 = __ldg(M + 1), m02 = __ldg(M + 2);
    float m10 = __ldg(M + 3), m11 = __ldg(M + 4), m12 = __ldg(M + 5);
    float m20 = __ldg(M + 6), m21 = __ldg(M + 7), m22 = __ldg(M + 8);

    const float4* vj = reinterpret_cast<const float4*>(vec + (size_t)s * 192) + l;
    const float4* vi = reinterpret_cast<const float4*>(vec + (size_t)r * 192) + l;
    float4 vj0 = __ldg(vj + 0),  vj1 = __ldg(vj + 16), vj2 = __ldg(vj + 32);
    float4 vi0 = __ldg(vi + 0),  vi1 = __ldg(vi + 16), vi2 = __ldg(vi + 32);

    float4 pj = __ldg(reinterpret_cast<const float4*>(g_p + (size_t)s * 64) + l);
    float4 pi = __ldg(reinterpret_cast<const float4*>(g_p + (size_t)r * 64) + l);
    float4 w  = __ldg(reinterpret_cast<const float4*>(vw) + l);

    float4 f0, f1, f2, S, d;
    f0.x = m00 * vj0.x + m01 * vj1.x + m02 * vj2.x;
    f0.y = m00 * vj0.y + m01 * vj1.y + m02 * vj2.y;
    f0.z = m00 * vj0.z + m01 * vj1.z + m02 * vj2.z;
    f0.w = m00 * vj0.w + m01 * vj1.w + m02 * vj2.w;
    f1.x = m10 * vj0.x + m11 * vj1.x + m12 * vj2.x;
    f1.y = m10 * vj0.y + m11 * vj1.y + m12 * vj2.y;
    f1.z = m10 * vj0.z + m11 * vj1.z + m12 * vj2.z;
    f1.w = m10 * vj0.w + m11 * vj1.w + m12 * vj2.w;
    f2.x = m20 * vj0.x + m21 * vj1.x + m22 * vj2.x;
    f2.y = m20 * vj0.y + m21 * vj1.y + m22 * vj2.y;
    f2.z = m20 * vj0.z + m21 * vj1.z + m22 * vj2.z;
    f2.w = m20 * vj0.w + m21 * vj1.w + m22 * vj2.w;

    S.x = vi0.x * f0.x + vi1.x * f1.x + vi2.x * f2.x;
    S.y = vi0.y * f0.y + vi1.y * f1.y + vi2.y * f2.y;
    S.z = vi0.z * f0.z + vi1.z * f1.z + vi2.z * f2.z;
    S.w = vi0.w * f0.w + vi1.w * f1.w + vi2.w * f2.w;

    d.x = w.x * w.x * pi.x * pj.x * S.x;
    d.y = w.y * w.y * pi.y * pj.y * S.y;
    d.z = w.z * w.z * pi.z * pj.z * S.z;
    d.w = w.w * w.w * pi.w * pj.w * S.w;

    float* dst = out + (size_t)r * 64 + 4 * l;
    asm volatile("red.global.add.v4.f32 [%0], {%1, %2, %3, %4};"
                 :: "l"(dst), "f"(d.x), "f"(d.y), "f"(d.z), "f"(d.w)
                 : "memory");
}

// ---------------------------------------------------------------------------
extern "C" void kernel_launch(void* const* d_in, const int* in_sizes, int n_in,
                              void* d_out, int out_size)
{
    const float* x         = (const float*)d_in[0];
    const float* vec       = (const float*)d_in[1];
    const int*   senders   = (const int*)  d_in[2];
    const int*   receivers = (const int*)  d_in[3];
    const float* im        = (const float*)d_in[4];
    const float* ln_scale  = (const float*)d_in[5];
    const float* ln_bias   = (const float*)d_in[6];
    const float* vln       = (const float*)d_in[7];
    const float* w1        = (const float*)d_in[8];
    const float* b1        = (const float*)d_in[9];
    const float* w2        = (const float*)d_in[10];
    const float* b2        = (const float*)d_in[11];

    int N = in_sizes[0] / CCH;
    int E = in_sizes[2];

    cudaMemsetAsync(d_out, 0, (size_t)out_size * sizeof(float));

    // node kernel: 8 warps/block, 4 nodes/warp -> 32 nodes/block
    const int smem = (64 * 128 + 128 * 64 + 8 * 4 * 64 + 8 * 4 * 128) * (int)sizeof(float);
    static bool attr_set = false;
    if (!attr_set) {
        cudaFuncSetAttribute(k_node, cudaFuncAttributeMaxDynamicSharedMemorySize, smem);
        attr_set = true;
    }
    int nblocks = (N + 31) / 32;
    k_node<<<nblocks, 256, smem>>>(x, ln_scale, ln_bias, w1, b1, w2, b2, N);

    // edge kernel: 16 threads/edge
    long long tot = (long long)E * 16;
    int eblocks = (int)((tot + 255) / 256);
    k_edge<<<eblocks, 256>>>(vec, senders, receivers, im, vln, (float*)d_out, E);
}

// round 2
// speedup vs baseline: 1.1252x; 1.1252x over previous
#include <cuda_runtime.h>
#include <cuda_bf16.h>

// PoleInteraction, q-fused form:
//   p = MLP(LayerNorm(x))
//   q[n,i,c] = vln[c] * p[n,c] * vec[n,i,c]
//   dEnergy[e,c] = sum_ij q[r,i,c] * M[e,i,j] * q[s,j,c]
//   dx = segment_sum(dEnergy, receivers)

#define NODES_MAX 50000
#define CCH 64

__device__ float g_q[NODES_MAX * 3 * CCH];  // fused w*p*vec field [N,3,64]

// ---------------------------------------------------------------------------
// K1: LayerNorm + MLP (64 -> 128 silu -> 64) + q epilogue.
// Warp per 4 nodes, weights in smem.
// ---------------------------------------------------------------------------
__global__ __launch_bounds__(256) void k_node(
    const float* __restrict__ x,
    const float* __restrict__ vec,
    const float* __restrict__ ln_s, const float* __restrict__ ln_b,
    const float* __restrict__ vw,
    const float* __restrict__ w1, const float* __restrict__ b1,
    const float* __restrict__ w2, const float* __restrict__ b2,
    int N)
{
    extern __shared__ float sm[];
    float* w1s = sm;                     // 64*128
    float* w2s = w1s + 64 * 128;         // 128*64
    float* xns = w2s + 128 * 64;         // 8 warps * 4 nodes * 64
    float* hs  = xns + 8 * 4 * 64;       // 8 warps * 4 nodes * 128

    int tid = threadIdx.x;
    for (int i = tid; i < (64 * 128) / 4; i += blockDim.x)
        reinterpret_cast<float4*>(w1s)[i] = reinterpret_cast<const float4*>(w1)[i];
    for (int i = tid; i < (128 * 64) / 4; i += blockDim.x)
        reinterpret_cast<float4*>(w2s)[i] = reinterpret_cast<const float4*>(w2)[i];
    __syncthreads();

    int warp = tid >> 5, lane = tid & 31;
    int node0 = (blockIdx.x * 8 + warp) * 4;
    if (node0 >= N) return;
    float* xn = xns + warp * 4 * 64;
    float* hh = hs  + warp * 4 * 128;

    float2 lns = reinterpret_cast<const float2*>(ln_s)[lane];
    float2 lnb = reinterpret_cast<const float2*>(ln_b)[lane];

    // LayerNorm for 4 nodes; thread owns channels 2*lane, 2*lane+1
    #pragma unroll
    for (int u = 0; u < 4; u++) {
        int n = node0 + u;
        float2 v = make_float2(0.f, 0.f);
        if (n < N) v = reinterpret_cast<const float2*>(x + (size_t)n * 64)[lane];
        float s  = v.x + v.y;
        float sq = v.x * v.x + v.y * v.y;
        #pragma unroll
        for (int o = 16; o; o >>= 1) {
            s  += __shfl_xor_sync(0xffffffffu, s,  o);
            sq += __shfl_xor_sync(0xffffffffu, sq, o);
        }
        float mean = s * (1.f / 64.f);
        float var  = sq * (1.f / 64.f) - mean * mean;
        float rstd = rsqrtf(var + 1e-5f);
        float2 o;
        o.x = (v.x - mean) * rstd * lns.x + lnb.x;
        o.y = (v.y - mean) * rstd * lns.y + lnb.y;
        reinterpret_cast<float2*>(xn + u * 64)[lane] = o;
    }
    __syncwarp();

    // Layer 1: thread computes h[4*lane .. 4*lane+3] for 4 nodes
    float4 bb1 = reinterpret_cast<const float4*>(b1)[lane];
    float4 acc0 = bb1, acc1 = bb1, acc2 = bb1, acc3 = bb1;
    #pragma unroll 4
    for (int c = 0; c < 64; c++) {
        float4 w = reinterpret_cast<float4*>(w1s + c * 128)[lane];
        float x0 = xn[0 * 64 + c], x1 = xn[1 * 64 + c];
        float x2 = xn[2 * 64 + c], x3 = xn[3 * 64 + c];
        acc0.x += x0 * w.x; acc0.y += x0 * w.y; acc0.z += x0 * w.z; acc0.w += x0 * w.w;
        acc1.x += x1 * w.x; acc1.y += x1 * w.y; acc1.z += x1 * w.z; acc1.w += x1 * w.w;
        acc2.x += x2 * w.x; acc2.y += x2 * w.y; acc2.z += x2 * w.z; acc2.w += x2 * w.w;
        acc3.x += x3 * w.x; acc3.y += x3 * w.y; acc3.z += x3 * w.z; acc3.w += x3 * w.w;
    }

    // silu + stage h
    {
        float4 a[4] = {acc0, acc1, acc2, acc3};
        #pragma unroll
        for (int u = 0; u < 4; u++) {
            float4 v = a[u];
            v.x = v.x / (1.f + __expf(-v.x));
            v.y = v.y / (1.f + __expf(-v.y));
            v.z = v.z / (1.f + __expf(-v.z));
            v.w = v.w / (1.f + __expf(-v.w));
            reinterpret_cast<float4*>(hh + u * 128)[lane] = v;
        }
    }
    __syncwarp();

    // Layer 2: thread computes p[2*lane], p[2*lane+1] for 4 nodes
    float2 bb2 = reinterpret_cast<const float2*>(b2)[lane];
    float2 p0 = bb2, p1 = bb2, p2 = bb2, p3 = bb2;
    #pragma unroll 4
    for (int k = 0; k < 128; k++) {
        float2 w = reinterpret_cast<float2*>(w2s + k * 64)[lane];
        float h0 = hh[0 * 128 + k], h1 = hh[1 * 128 + k];
        float h2 = hh[2 * 128 + k], h3 = hh[3 * 128 + k];
        p0.x += h0 * w.x; p0.y += h0 * w.y;
        p1.x += h1 * w.x; p1.y += h1 * w.y;
        p2.x += h2 * w.x; p2.y += h2 * w.y;
        p3.x += h3 * w.x; p3.y += h3 * w.y;
    }

    // Epilogue: q[n,i,c] = vln[c] * p[n,c] * vec[n,i,c]
    float2 wv = reinterpret_cast<const float2*>(vw)[lane];
    {
        float2 p[4] = {p0, p1, p2, p3};
        #pragma unroll
        for (int u = 0; u < 4; u++) {
            int n = node0 + u;
            if (n >= N) continue;
            float2 pw;
            pw.x = p[u].x * wv.x;
            pw.y = p[u].y * wv.y;
            const float2* vsrc = reinterpret_cast<const float2*>(vec + (size_t)n * 192);
            float2*       qdst = reinterpret_cast<float2*>(g_q + (size_t)n * 192);
            #pragma unroll
            for (int i = 0; i < 3; i++) {
                float2 v = vsrc[i * 32 + lane];
                float2 qq;
                qq.x = pw.x * v.x;
                qq.y = pw.y * v.y;
                qdst[i * 32 + lane] = qq;
            }
        }
    }
}

// ---------------------------------------------------------------------------
// K2: edge phase on fused q. 16 threads/edge, thread owns 4 channels.
//   f_i = sum_j M[i][j]*q_s[j] ;  dEnergy = sum_i q_r[i]*f_i
// ---------------------------------------------------------------------------
__global__ __launch_bounds__(256) void k_edge(
    const int*   __restrict__ senders,
    const int*   __restrict__ receivers,
    const float* __restrict__ Mm,
    float* __restrict__ out,
    int E)
{
    int t = blockIdx.x * blockDim.x + threadIdx.x;
    int e = t >> 4;
    if (e >= E) return;
    int l = t & 15;

    int s = __ldg(senders + e);
    int r = __ldg(receivers + e);

    const float* M = Mm + (size_t)e * 9;
    float m00 = __ldg(M + 0), m01 = __ldg(M + 1), m02 = __ldg(M + 2);
    float m10 = __ldg(M + 3), m11 = __ldg(M + 4), m12 = __ldg(M + 5);
    float m20 = __ldg(M + 6), m21 = __ldg(M + 7), m22 = __ldg(M + 8);

    const float4* qj = reinterpret_cast<const float4*>(g_q + (size_t)s * 192) + l;
    const float4* qi = reinterpret_cast<const float4*>(g_q + (size_t)r * 192) + l;
    float4 qj0 = __ldg(qj + 0), qj1 = __ldg(qj + 16), qj2 = __ldg(qj + 32);
    float4 qi0 = __ldg(qi + 0), qi1 = __ldg(qi + 16), qi2 = __ldg(qi + 32);

    float4 f0, f1, f2, d;
    f0.x = m00 * qj0.x + m01 * qj1.x + m02 * qj2.x;
    f0.y = m00 * qj0.y + m01 * qj1.y + m02 * qj2.y;
    f0.z = m00 * qj0.z + m01 * qj1.z + m02 * qj2.z;
    f0.w = m00 * qj0.w + m01 * qj1.w + m02 * qj2.w;
    f1.x = m10 * qj0.x + m11 * qj1.x + m12 * qj2.x;
    f1.y = m10 * qj0.y + m11 * qj1.y + m12 * qj2.y;
    f1.z = m10 * qj0.z + m11 * qj1.z + m12 * qj2.z;
    f1.w = m10 * qj0.w + m11 * qj1.w + m12 * qj2.w;
    f2.x = m20 * qj0.x + m21 * qj1.x + m22 * qj2.x;
    f2.y = m20 * qj0.y + m21 * qj1.y + m22 * qj2.y;
    f2.z = m20 * qj0.z + m21 * qj1.z + m22 * qj2.z;
    f2.w = m20 * qj0.w + m21 * qj1.w + m22 * qj2.w;

    d.x = qi0.x * f0.x + qi1.x * f1.x + qi2.x * f2.x;
    d.y = qi0.y * f0.y + qi1.y * f1.y + qi2.y * f2.y;
    d.z = qi0.z * f0.z + qi1.z * f1.z + qi2.z * f2.z;
    d.w = qi0.w * f0.w + qi1.w * f1.w + qi2.w * f2.w;

    float* dst = out + (size_t)r * 64 + 4 * l;
    asm volatile("red.global.add.v4.f32 [%0], {%1, %2, %3, %4};"
                 :: "l"(dst), "f"(d.x), "f"(d.y), "f"(d.z), "f"(d.w)
                 : "memory");
}

// ---------------------------------------------------------------------------
extern "C" void kernel_launch(void* const* d_in, const int* in_sizes, int n_in,
                              void* d_out, int out_size)
{
    const float* x         = (const float*)d_in[0];
    const float* vec       = (const float*)d_in[1];
    const int*   senders   = (const int*)  d_in[2];
    const int*   receivers = (const int*)  d_in[3];
    const float* im        = (const float*)d_in[4];
    const float* ln_scale  = (const float*)d_in[5];
    const float* ln_bias   = (const float*)d_in[6];
    const float* vln       = (const float*)d_in[7];
    const float* w1        = (const float*)d_in[8];
    const float* b1        = (const float*)d_in[9];
    const float* w2        = (const float*)d_in[10];
    const float* b2        = (const float*)d_in[11];

    int N = in_sizes[0] / CCH;
    int E = in_sizes[2];

    cudaMemsetAsync(d_out, 0, (size_t)out_size * sizeof(float));

    const int smem = (64 * 128 + 128 * 64 + 8 * 4 * 64 + 8 * 4 * 128) * (int)sizeof(float);
    static bool attr_set = false;
    if (!attr_set) {
        cudaFuncSetAttribute(k_node, cudaFuncAttributeMaxDynamicSharedMemorySize, smem);
        attr_set = true;
    }
    int nblocks = (N + 31) / 32;
    k_node<<<nblocks, 256, smem>>>(x, vec, ln_scale, ln_bias, vln, w1, b1, w2, b2, N);

    long long tot = (long long)E * 16;
    int eblocks = (int)((tot + 255) / 256);
    k_edge<<<eblocks, 256>>>(senders, receivers, im, (float*)d_out, E);
}